// round 3
// baseline (speedup 1.0000x reference)
#include <cuda_runtime.h>
#include <cstdint>

// Problem constants
#define B_    64
#define CIN_  64
#define T_    4096
#define F_    128
#define K_    64
#define TOUT_ 4033          // T - K + 1
#define TILE_ 192           // conv outputs per CTA tile
#define YLEN_ 256           // TILE_ + K_ (y values needed per tile)
#define NT_   22            // ceil(TOUT_/TILE_)
#define YSTR_ 268           // padded y row stride (floats)

// smem layout (floats)
#define OFF_X    0                       // 64*256  = 16384
#define OFF_Y    16384                   // 32*268  = 8576
#define OFF_W    (16384+8576)            // 2304 (spatT 64x36 / conv_w 32x64)
#define OFF_SSQ  (OFF_W+2304)            // 256
#define OFF_INV  (OFF_SSQ+256)           // 192
#define SMEM_FLOATS (OFF_INV+192)        // 27712 -> 110848 bytes

__device__ float g_wf[F_];
__device__ float g_bias_sum;
__device__ float g_partial[B_ * NT_];

// ---------------------------------------------------------------------------
// Setup: per-filter combined weight factor + bias sum
// ---------------------------------------------------------------------------
__global__ void setup_kernel(const float* __restrict__ conv_w,
                             const float* __restrict__ spat_w,
                             const float* __restrict__ weight,
                             const float* __restrict__ bias) {
    int f = threadIdx.x;  // 128 threads
    float sc = 0.f, ss = 0.f;
    #pragma unroll 8
    for (int k = 0; k < K_; k++) { float v = conv_w[f * K_ + k]; sc += v * v; }
    #pragma unroll 8
    for (int c = 0; c < CIN_; c++) { float v = spat_w[f * CIN_ + c]; ss += v * v; }
    float norm_w = sqrtf(sc) * sqrtf(ss);
    // scale = sqrt(CIN*K) = 64 exactly; fold 1/Tout for the mean
    g_wf[f] = weight[f] * 64.0f / (norm_w * (float)TOUT_);

    __shared__ float sb[F_];
    sb[f] = bias[f];
    __syncthreads();
    for (int s = F_ / 2; s > 0; s >>= 1) {
        if (f < s) sb[f] += sb[f + s];
        __syncthreads();
    }
    if (f == 0) g_bias_sum = sb[0];
}

// ---------------------------------------------------------------------------
// Main fused kernel: one CTA per (t-tile, batch)
// ---------------------------------------------------------------------------
__global__ __launch_bounds__(256, 2)
void main_kernel(const float* __restrict__ x,
                 const float* __restrict__ conv_w,
                 const float* __restrict__ spat_w) {
    extern __shared__ float sm[];
    float* x_s  = sm + OFF_X;     // [64][256]
    float* y_s  = sm + OFF_Y;     // [32][YSTR_]
    float* wbuf = sm + OFF_W;     // spatT [64][36] then conv_w [32][64]
    float* ssq  = sm + OFF_SSQ;   // [256]
    float* invn = sm + OFF_INV;   // [192]

    const int tid  = threadIdx.x;
    const int b    = blockIdx.y;
    const int tile = blockIdx.x;
    const int t0g  = tile * TILE_;

    // ---- stage x tile (zero-fill past T) ----
    const float* xb = x + (size_t)b * CIN_ * T_;
    #pragma unroll
    for (int r = 0; r < 16; r++) {
        int idx = r * 256 + tid;
        int c   = idx >> 6;
        int t4  = (idx & 63) * 4;
        int tg  = t0g + t4;
        float4 v;
        if (tg + 3 < T_) {
            v = *(const float4*)(xb + c * T_ + tg);
        } else {
            v.x = (tg + 0 < T_) ? xb[c * T_ + tg + 0] : 0.f;
            v.y = (tg + 1 < T_) ? xb[c * T_ + tg + 1] : 0.f;
            v.z = (tg + 2 < T_) ? xb[c * T_ + tg + 2] : 0.f;
            v.w = (tg + 3 < T_) ? xb[c * T_ + tg + 3] : 0.f;
        }
        *(float4*)(x_s + c * 256 + t4) = v;
    }
    __syncthreads();

    // ---- per-t channel energy ----
    {
        float s = 0.f;
        #pragma unroll 8
        for (int c = 0; c < CIN_; c++) { float v = x_s[c * 256 + tid]; s += v * v; }
        ssq[tid] = s;
    }
    __syncthreads();
    // ---- sliding-window norm -> 1/norm ----
    if (tid < TILE_) {
        float s = 0.f;
        #pragma unroll 8
        for (int k = 0; k < K_; k++) s += ssq[tid + k];
        invn[tid] = (s > 0.f) ? rsqrtf(s) : 0.f;
    }

    const int lane = tid & 31;
    const int wfch = tid >> 5;       // 0..7 -> filter sub-chunk
    const int ta   = 4 * lane;
    const int tb   = 128 + 4 * lane;
    const int fb4  = wfch * 4;

    float psum = 0.f;

    for (int g = 0; g < 4; g++) {
        const int gbase = g * 32;
        __syncthreads();  // protect wbuf & y_s from previous group

        // stage spatT: wbuf[c*36 + fg] = spat_w[(gbase+fg)*64 + c]
        #pragma unroll
        for (int r = 0; r < 8; r++) {
            int idx = r * 256 + tid;        // 0..2047
            int fg  = idx >> 6;
            int c   = idx & 63;
            wbuf[c * 36 + fg] = spat_w[(gbase + fg) * CIN_ + c];
        }
        __syncthreads();

        // ---- y = spat_w @ x  (register tile: 4 filters x 8 t) ----
        float aa[4][4], ab[4][4];
        #pragma unroll
        for (int i = 0; i < 4; i++)
            #pragma unroll
            for (int j = 0; j < 4; j++) { aa[i][j] = 0.f; ab[i][j] = 0.f; }

        #pragma unroll 4
        for (int c = 0; c < CIN_; c++) {
            float4 xa = *(float4*)(x_s + c * 256 + ta);
            float4 xv = *(float4*)(x_s + c * 256 + tb);
            float4 sp = *(float4*)(wbuf + c * 36 + fb4);
            float spv[4] = {sp.x, sp.y, sp.z, sp.w};
            float xav[4] = {xa.x, xa.y, xa.z, xa.w};
            float xbv[4] = {xv.x, xv.y, xv.z, xv.w};
            #pragma unroll
            for (int i = 0; i < 4; i++) {
                #pragma unroll
                for (int j = 0; j < 4; j++) {
                    aa[i][j] = fmaf(spv[i], xav[j], aa[i][j]);
                    ab[i][j] = fmaf(spv[i], xbv[j], ab[i][j]);
                }
            }
        }
        #pragma unroll
        for (int i = 0; i < 4; i++) {
            *(float4*)(y_s + (fb4 + i) * YSTR_ + ta) =
                make_float4(aa[i][0], aa[i][1], aa[i][2], aa[i][3]);
            *(float4*)(y_s + (fb4 + i) * YSTR_ + tb) =
                make_float4(ab[i][0], ab[i][1], ab[i][2], ab[i][3]);
        }
        __syncthreads();

        // stage conv_w for this group: wbuf[f*64 + k]
        #pragma unroll
        for (int r = 0; r < 8; r++) {
            int idx = r * 256 + tid;
            wbuf[idx] = conv_w[gbase * K_ + idx];
        }
        __syncthreads();

        // ---- temporal conv + |.|/norm accumulate ----
        #pragma unroll
        for (int rep = 0; rep < 6; rep++) {
            int idx = rep * 256 + tid;      // 0..1535
            int f   = idx / 48;             // 0..31
            int tl0 = (idx % 48) * 4;       // 0..188
            const float* yrow = y_s + f * YSTR_;

            float4 w4 = *(const float4*)(yrow + tl0);
            float w0 = w4.x, w1 = w4.y, w2 = w4.z, w3 = w4.w;
            float c0 = 0.f, c1 = 0.f, c2 = 0.f, c3 = 0.f;

            #pragma unroll
            for (int k4 = 0; k4 < K_; k4 += 4) {
                float4 n  = *(const float4*)(yrow + tl0 + k4 + 4);
                float4 cw = *(const float4*)(wbuf + f * K_ + k4);
                c0 = fmaf(cw.x, w0, fmaf(cw.y, w1, fmaf(cw.z, w2, fmaf(cw.w, w3, c0))));
                c1 = fmaf(cw.x, w1, fmaf(cw.y, w2, fmaf(cw.z, w3, fmaf(cw.w, n.x, c1))));
                c2 = fmaf(cw.x, w2, fmaf(cw.y, w3, fmaf(cw.z, n.x, fmaf(cw.w, n.y, c2))));
                c3 = fmaf(cw.x, w3, fmaf(cw.y, n.x, fmaf(cw.z, n.y, fmaf(cw.w, n.z, c3))));
                w0 = n.x; w1 = n.y; w2 = n.z; w3 = n.w;
            }

            float wf_f = g_wf[gbase + f];
            int tg = t0g + tl0;
            if (tg + 0 < TOUT_) psum = fmaf(wf_f, fabsf(c0) * invn[tl0 + 0], psum);
            if (tg + 1 < TOUT_) psum = fmaf(wf_f, fabsf(c1) * invn[tl0 + 1], psum);
            if (tg + 2 < TOUT_) psum = fmaf(wf_f, fabsf(c2) * invn[tl0 + 2], psum);
            if (tg + 3 < TOUT_) psum = fmaf(wf_f, fabsf(c3) * invn[tl0 + 3], psum);
        }
    }

    // ---- block reduce -> partial ----
    #pragma unroll
    for (int o = 16; o > 0; o >>= 1)
        psum += __shfl_xor_sync(0xffffffffu, psum, o);
    __syncthreads();               // ssq no longer needed; reuse as scratch
    if (lane == 0) ssq[wfch] = psum;
    __syncthreads();
    if (tid == 0) {
        float s = 0.f;
        #pragma unroll
        for (int i = 0; i < 8; i++) s += ssq[i];
        g_partial[b * NT_ + tile] = s;
    }
}

// ---------------------------------------------------------------------------
// Final reduction: out[b] = bias_sum + sum over tiles
// ---------------------------------------------------------------------------
__global__ void finish_kernel(float* __restrict__ out) {
    int b = threadIdx.x;  // 64 threads
    float s = g_bias_sum;
    #pragma unroll
    for (int i = 0; i < NT_; i++) s += g_partial[b * NT_ + i];
    out[b] = s;
}

// ---------------------------------------------------------------------------
extern "C" void kernel_launch(void* const* d_in, const int* in_sizes, int n_in,
                              void* d_out, int out_size) {
    const float* x      = (const float*)d_in[0];  // [64,64,4096]
    const float* conv_w = (const float*)d_in[1];  // [128,64]
    const float* spat_w = (const float*)d_in[2];  // [128,64]
    const float* weight = (const float*)d_in[3];  // [128]
    const float* bias   = (const float*)d_in[4];  // [128]
    float* out = (float*)d_out;                   // [64]

    static bool attr_set = false;
    // cudaFuncSetAttribute is idempotent and not a stream op; safe pre-capture
    // and during capture. Set every call to stay stateless.
    cudaFuncSetAttribute(main_kernel,
                         cudaFuncAttributeMaxDynamicSharedMemorySize,
                         SMEM_FLOATS * sizeof(float));
    (void)attr_set;

    setup_kernel<<<1, 128>>>(conv_w, spat_w, weight, bias);
    dim3 grid(NT_, B_);
    main_kernel<<<grid, 256, SMEM_FLOATS * sizeof(float)>>>(x, conv_w, spat_w);
    finish_kernel<<<1, 64>>>(out);
}